// round 4
// baseline (speedup 1.0000x reference)
#include <cuda_runtime.h>

#define NN 50000
#define EE 640000
#define FF 128
#define GG 256
#define NC 10

// ---------------- scratch (static device globals; no allocation) ----------------
__device__ float g_x[NN * FF];        // node features (BN'd, then squash output per layer)
__device__ float g_h[NN * FF];        // x @ W
__device__ float g_stats[2 * FF];     // column sum / sumsq for BN
__device__ float g_deg[NN];
__device__ float g_dinv[NN];
__device__ float g_selfw[NN];         // dinv^2 (self-loop norm)
__device__ int   g_rowcnt[NN];
__device__ int   g_rowptr[NN + 1];
__device__ int   g_cursor[NN];
__device__ int   g_col[EE];
__device__ float g_wgt[EE];
__device__ float g_att[NN];
__device__ int   g_goff[GG + 1];
__device__ float g_rep[GG * 3 * FF];
__device__ int   g_src[EE];
__device__ int   g_dst[EE];
__device__ int   g_batch[NN];
__device__ int   g_is32_edge;
__device__ int   g_is32_batch;

// ---------------- dtype detection (int64 metadata may actually be int32) ----------------
__global__ void k_detect(const long long* __restrict__ ei, const long long* __restrict__ batch) {
    if (threadIdx.x == 0 && blockIdx.x == 0) {
        int is32 = 0;
        // stay within first EE/2 int64 slots: in-bounds for either dtype
        for (int i = 0; i < 16; i++) {
            long long v = ei[i * 37];
            if (v < 0 || v >= (long long)NN) is32 = 1;
        }
        g_is32_edge = is32;
        // batch is sorted; tail value must be < GG. Index NN/2-1 is in-bounds either way.
        long long vb = batch[NN / 2 - 1];
        g_is32_batch = (vb < 0 || vb >= (long long)GG) ? 1 : 0;
    }
}

__global__ void k_conv_edges(const void* __restrict__ ei) {
    int e = blockIdx.x * blockDim.x + threadIdx.x;
    if (e >= EE) return;
    int s, d;
    if (g_is32_edge) {
        const int* p = (const int*)ei;
        s = p[e]; d = p[EE + e];
    } else {
        const long long* p = (const long long*)ei;
        s = (int)p[e]; d = (int)p[EE + e];
    }
    s = min(max(s, 0), NN - 1);
    d = min(max(d, 0), NN - 1);
    g_src[e] = s; g_dst[e] = d;
}

__global__ void k_conv_batch(const void* __restrict__ batch) {
    int i = blockIdx.x * blockDim.x + threadIdx.x;
    if (i >= NN) return;
    int b;
    if (g_is32_batch) b = ((const int*)batch)[i];
    else              b = (int)((const long long*)batch)[i];
    g_batch[i] = min(max(b, 0), GG - 1);
}

// ---------------- init ----------------
__global__ void k_init() {
    int i = blockIdx.x * blockDim.x + threadIdx.x;
    if (i < NN) { g_rowcnt[i] = 0; g_deg[i] = 1.0f; }   // deg starts at 1 (self loop)
    if (i < 2 * FF) g_stats[i] = 0.0f;
    if (i < GG * 3 * FF) g_rep[i] = 0.0f;
}

// ---------------- BN stats: per-feature sum & sumsq ----------------
__global__ void k_bn_stats(const float4* __restrict__ x4) {
    int f4 = threadIdx.x & 31;          // float4 chunk (features f4*4 .. f4*4+3)
    int rsub = threadIdx.x >> 5;        // 0..7
    float4 s = make_float4(0, 0, 0, 0);
    float4 q = make_float4(0, 0, 0, 0);
    for (int r = blockIdx.x * 8 + rsub; r < NN; r += gridDim.x * 8) {
        float4 v = x4[r * 32 + f4];
        s.x += v.x; s.y += v.y; s.z += v.z; s.w += v.w;
        q.x += v.x * v.x; q.y += v.y * v.y; q.z += v.z * v.z; q.w += v.w * v.w;
    }
    __shared__ float ss[FF], sq[FF];
    if (threadIdx.x < FF) { ss[threadIdx.x] = 0.f; sq[threadIdx.x] = 0.f; }
    __syncthreads();
    atomicAdd(&ss[f4 * 4 + 0], s.x); atomicAdd(&ss[f4 * 4 + 1], s.y);
    atomicAdd(&ss[f4 * 4 + 2], s.z); atomicAdd(&ss[f4 * 4 + 3], s.w);
    atomicAdd(&sq[f4 * 4 + 0], q.x); atomicAdd(&sq[f4 * 4 + 1], q.y);
    atomicAdd(&sq[f4 * 4 + 2], q.z); atomicAdd(&sq[f4 * 4 + 3], q.w);
    __syncthreads();
    if (threadIdx.x < FF) {
        atomicAdd(&g_stats[threadIdx.x], ss[threadIdx.x]);
        atomicAdd(&g_stats[FF + threadIdx.x], sq[threadIdx.x]);
    }
}

// ---------------- BN apply ----------------
__global__ void k_bn_apply(const float4* __restrict__ x4,
                           const float* __restrict__ gamma,
                           const float* __restrict__ beta) {
    int idx = blockIdx.x * blockDim.x + threadIdx.x;
    if (idx >= NN * 32) return;
    int f4 = idx & 31;
    float4 v = x4[idx];
    float4 o;
    float invN = 1.0f / (float)NN;
    #pragma unroll
    for (int c = 0; c < 4; c++) {
        int f = f4 * 4 + c;
        float mean = g_stats[f] * invN;
        float var = g_stats[FF + f] * invN - mean * mean;
        float istd = rsqrtf(var + 1e-5f);
        float vi = (c == 0) ? v.x : (c == 1) ? v.y : (c == 2) ? v.z : v.w;
        float r = (vi - mean) * istd * gamma[f] + beta[f];
        if (c == 0) o.x = r; else if (c == 1) o.y = r; else if (c == 2) o.z = r; else o.w = r;
    }
    ((float4*)g_x)[idx] = o;
}

// ---------------- degree + row histogram ----------------
__global__ void k_deg() {
    int e = blockIdx.x * blockDim.x + threadIdx.x;
    if (e >= EE) return;
    int s = g_src[e], d = g_dst[e];
    if (s != d) {
        atomicAdd(&g_deg[d], 1.0f);
        atomicAdd(&g_rowcnt[d], 1);
    }
}

__global__ void k_dinv() {
    int i = blockIdx.x * blockDim.x + threadIdx.x;
    if (i >= NN) return;
    float di = rsqrtf(g_deg[i]);
    g_dinv[i] = di;
    g_selfw[i] = di * di;
}

// ---------------- single-block exclusive scan over rowcnt -> rowptr/cursor ----------------
__global__ void k_scan() {
    __shared__ int sh[1024];
    __shared__ int carry;
    if (threadIdx.x == 0) carry = 0;
    __syncthreads();
    for (int base = 0; base < NN; base += 1024) {
        int i = base + threadIdx.x;
        int v = (i < NN) ? g_rowcnt[i] : 0;
        sh[threadIdx.x] = v;
        __syncthreads();
        for (int off = 1; off < 1024; off <<= 1) {
            int t = (threadIdx.x >= off) ? sh[threadIdx.x - off] : 0;
            __syncthreads();
            sh[threadIdx.x] += t;
            __syncthreads();
        }
        int excl = sh[threadIdx.x] - v;
        if (i < NN) { g_rowptr[i] = carry + excl; g_cursor[i] = carry + excl; }
        __syncthreads();
        if (threadIdx.x == 1023) carry += sh[1023];
        __syncthreads();
    }
    if (threadIdx.x == 0) g_rowptr[NN] = carry;
}

// ---------------- CSR scatter with edge norms ----------------
__global__ void k_scatter() {
    int e = blockIdx.x * blockDim.x + threadIdx.x;
    if (e >= EE) return;
    int s = g_src[e], d = g_dst[e];
    if (s != d) {
        int p = atomicAdd(&g_cursor[d], 1);
        g_col[p] = s;
        g_wgt[p] = g_dinv[s] * g_dinv[d];
    }
}

// ---------------- graph segment offsets from sorted batch ----------------
__global__ void k_goff() {
    int i = blockIdx.x * blockDim.x + threadIdx.x;
    if (i >= NN) return;
    int b = g_batch[i];
    int bp = (i == 0) ? -1 : g_batch[i - 1];
    for (int g = bp + 1; g <= b; g++) g_goff[g] = i;
    if (i == NN - 1) {
        for (int g = b + 1; g <= GG; g++) g_goff[g] = NN;
    }
}

// ---------------- GEMM: g_h[M,128] = g_x[M,128] @ W[128,128] ----------------
__global__ void __launch_bounds__(256) k_gemm(const float* __restrict__ W) {
    __shared__ float xs[8][132];   // transposed x tile, padded (conflict-free)
    __shared__ float ws[8][128];
    int tid = threadIdx.x;
    int tx = tid & 15, ty = tid >> 4;
    int row0 = blockIdx.x * 128;
    int lm = tid >> 1;             // row within tile
    int lk = (tid & 1) * 4;        // k sub-offset
    int wk = tid >> 5;             // W tile row
    int wc = (tid & 31) * 4;       // W tile col

    float acc[8][8];
    #pragma unroll
    for (int i = 0; i < 8; i++)
        #pragma unroll
        for (int j = 0; j < 8; j++) acc[i][j] = 0.f;

    for (int k0 = 0; k0 < 128; k0 += 8) {
        float4 xv = make_float4(0, 0, 0, 0);
        int gr = row0 + lm;
        if (gr < NN) xv = *(const float4*)&g_x[gr * 128 + k0 + lk];
        xs[lk + 0][lm] = xv.x; xs[lk + 1][lm] = xv.y;
        xs[lk + 2][lm] = xv.z; xs[lk + 3][lm] = xv.w;
        *(float4*)&ws[wk][wc] = *(const float4*)&W[(k0 + wk) * 128 + wc];
        __syncthreads();
        #pragma unroll
        for (int k = 0; k < 8; k++) {
            float a[8], b[8];
            *(float4*)(a)     = *(const float4*)&xs[k][ty * 8];
            *(float4*)(a + 4) = *(const float4*)&xs[k][ty * 8 + 4];
            *(float4*)(b)     = *(const float4*)&ws[k][tx * 8];
            *(float4*)(b + 4) = *(const float4*)&ws[k][tx * 8 + 4];
            #pragma unroll
            for (int i = 0; i < 8; i++)
                #pragma unroll
                for (int j = 0; j < 8; j++) acc[i][j] += a[i] * b[j];
        }
        __syncthreads();
    }
    #pragma unroll
    for (int i = 0; i < 8; i++) {
        int gr = row0 + ty * 8 + i;
        if (gr < NN) {
            float4 o0 = make_float4(acc[i][0], acc[i][1], acc[i][2], acc[i][3]);
            float4 o1 = make_float4(acc[i][4], acc[i][5], acc[i][6], acc[i][7]);
            *(float4*)&g_h[gr * 128 + tx * 8] = o0;
            *(float4*)&g_h[gr * 128 + tx * 8 + 4] = o1;
        }
    }
}

// ---------------- fused SpMM + bias + squash + attention dot ----------------
__global__ void k_spmm(const float* __restrict__ bias, const float* __restrict__ watt) {
    int warp = blockIdx.x * (blockDim.x >> 5) + (threadIdx.x >> 5);
    int lane = threadIdx.x & 31;
    if (warp >= NN) return;
    const float4* __restrict__ h4 = (const float4*)g_h;
    int d = warp;
    float4 hv = h4[d * 32 + lane];
    float sw = g_selfw[d];
    float4 acc = make_float4(sw * hv.x, sw * hv.y, sw * hv.z, sw * hv.w);
    int beg = g_rowptr[d], end = g_rowptr[d + 1];
    for (int base = beg; base < end; base += 32) {
        int e = base + lane;
        int c = 0; float ww = 0.f;
        if (e < end) { c = g_col[e]; ww = g_wgt[e]; }
        int cnt = end - base; if (cnt > 32) cnt = 32;
        for (int j = 0; j < cnt; j++) {
            int s = __shfl_sync(0xffffffffu, c, j);
            float wj = __shfl_sync(0xffffffffu, ww, j);
            float4 v = h4[s * 32 + lane];
            acc.x += wj * v.x; acc.y += wj * v.y;
            acc.z += wj * v.z; acc.w += wj * v.w;
        }
    }
    float4 b4 = ((const float4*)bias)[lane];
    acc.x += b4.x; acc.y += b4.y; acc.z += b4.z; acc.w += b4.w;
    float n2 = acc.x * acc.x + acc.y * acc.y + acc.z * acc.z + acc.w * acc.w;
    #pragma unroll
    for (int o = 16; o; o >>= 1) n2 += __shfl_xor_sync(0xffffffffu, n2, o);
    float scale = (n2 / (1.0f + n2)) * rsqrtf(n2 + 1e-8f);
    float4 xo = make_float4(scale * acc.x, scale * acc.y, scale * acc.z, scale * acc.w);
    ((float4*)g_x)[d * 32 + lane] = xo;
    float4 wa = ((const float4*)watt)[lane];
    float av = xo.x * wa.x + xo.y * wa.y + xo.z * wa.z + xo.w * wa.w;
    #pragma unroll
    for (int o = 16; o; o >>= 1) av += __shfl_xor_sync(0xffffffffu, av, o);
    if (lane == 0) g_att[d] = av;
}

// ---------------- per-graph readout (wsum / mean / max) ----------------
__global__ void k_readout() {
    int g = blockIdx.x, f = threadIdx.x;
    int s = g_goff[g], e = g_goff[g + 1];
    float wsum = 0.f, ssum = 0.f, mx = -3.402823e38f;
    #pragma unroll 4
    for (int i = s; i < e; i++) {
        float v = g_x[i * FF + f];
        float a = g_att[i];
        wsum += a * v;
        ssum += v;
        mx = fmaxf(mx, v);
    }
    float cnt = (float)(e - s);
    if (cnt < 1.0f) cnt = 1.0f;
    g_rep[g * 384 + f]       += wsum;
    g_rep[g * 384 + 128 + f] += ssum / cnt;
    g_rep[g * 384 + 256 + f] += (e > s) ? mx : 0.f;
}

// ---------------- MLP head + log_softmax ----------------
__global__ void k_head(const float* __restrict__ w1, const float* __restrict__ b1,
                       const float* __restrict__ w2, const float* __restrict__ b2,
                       float* __restrict__ out) {
    int g = blockIdx.x, t = threadIdx.x;
    __shared__ float srep[384];
    __shared__ float sh1[128];
    __shared__ float slog[16];
    for (int k = t; k < 384; k += 128) srep[k] = g_rep[g * 384 + k];
    __syncthreads();
    float acc = b1[t];
    #pragma unroll 8
    for (int k = 0; k < 384; k++) acc += srep[k] * w1[k * 128 + t];
    sh1[t] = fmaxf(acc, 0.f);
    __syncthreads();
    if (t < NC) {
        float a2 = b2[t];
        #pragma unroll 8
        for (int k = 0; k < 128; k++) a2 += sh1[k] * w2[k * NC + t];
        slog[t] = a2;
    }
    __syncthreads();
    if (t < NC) {
        float m = -3.402823e38f;
        for (int k = 0; k < NC; k++) m = fmaxf(m, slog[k]);
        float s = 0.f;
        for (int k = 0; k < NC; k++) s += expf(slog[k] - m);
        out[g * NC + t] = slog[t] - m - logf(s);
    }
}

// ---------------- launch ----------------
extern "C" void kernel_launch(void* const* d_in, const int* in_sizes, int n_in,
                              void* d_out, int out_size) {
    const float*     x      = (const float*)d_in[0];
    const void*      ei     = d_in[1];
    const void*      batch  = d_in[2];
    const float*     bn_g   = (const float*)d_in[3];
    const float*     bn_b   = (const float*)d_in[4];
    const float*     gcn_w  = (const float*)d_in[5];
    const float*     gcn_b  = (const float*)d_in[6];
    const float*     w_att  = (const float*)d_in[7];
    const float*     l1w    = (const float*)d_in[8];
    const float*     l1b    = (const float*)d_in[9];
    const float*     l2w    = (const float*)d_in[10];
    const float*     l2b    = (const float*)d_in[11];
    float* out = (float*)d_out;

    k_detect<<<1, 32>>>((const long long*)ei, (const long long*)batch);
    k_conv_edges<<<(EE + 255) / 256, 256>>>(ei);
    k_conv_batch<<<(NN + 255) / 256, 256>>>(batch);
    k_init<<<(GG * 3 * FF + 255) / 256, 256>>>();
    k_bn_stats<<<128, 256>>>((const float4*)x);
    k_bn_apply<<<(NN * 32 + 255) / 256, 256>>>((const float4*)x, bn_g, bn_b);
    k_deg<<<(EE + 255) / 256, 256>>>();
    k_dinv<<<(NN + 255) / 256, 256>>>();
    k_scan<<<1, 1024>>>();
    k_scatter<<<(EE + 255) / 256, 256>>>();
    k_goff<<<(NN + 255) / 256, 256>>>();

    for (int l = 0; l < 3; l++) {
        k_gemm<<<(NN + 127) / 128, 256>>>(gcn_w + l * FF * FF);
        k_spmm<<<(NN + 7) / 8, 256>>>(gcn_b + l * FF, w_att + l * FF);
        k_readout<<<GG, 128>>>();
    }
    k_head<<<GG, 128>>>(l1w, l1b, l2w, l2b, out);
}